// round 11
// baseline (speedup 1.0000x reference)
#include <cuda_runtime.h>
#include <cstdint>

#define SEQ    2048
#define BATCH  4096
#define IN     4
#define HID    3
#define UNR    16                 // timesteps per group
#define XS     4                  // x smem pipeline stages
#define RD     8                  // h ring depth (groups)
#define NGRP   (SEQ / UNR)        // 128 groups

// smem layout (dynamic): xs | hring | counters
#define XS_BYTES   (XS * UNR * 32 * 16)        // 32768
#define HR_BYTES   (RD * UNR * 96 * 4)         // 49152
#define CTR_OFF    (XS_BYTES + HR_BYTES)       // 81920
#define SMEM_TOTAL (CTR_OFF + 32)

typedef unsigned long long u64;

// ---- packed f32x2 helpers ----
__device__ __forceinline__ u64 pack2(float lo, float hi) {
    u64 r; asm("mov.b64 %0, {%1, %2};" : "=l"(r) : "f"(lo), "f"(hi)); return r;
}
__device__ __forceinline__ u64 bcast2(float v) {
    u64 r; asm("mov.b64 %0, {%1, %1};" : "=l"(r) : "f"(v)); return r;
}
__device__ __forceinline__ u64 fma2(u64 a, u64 b, u64 c) {
    u64 d; asm("fma.rn.f32x2 %0, %1, %2, %3;" : "=l"(d) : "l"(a), "l"(b), "l"(c)); return d;
}
__device__ __forceinline__ float2 unpack2(u64 v) {
    float2 r; asm("mov.b64 {%0, %1}, %2;" : "=f"(r.x), "=f"(r.y) : "l"(v)); return r;
}

// ---- cp.async ----
__device__ __forceinline__ void cp_async16(void* smem_dst, const void* gmem_src) {
    uint32_t s;
    asm("{ .reg .u64 t; cvta.to.shared.u64 t, %1; cvt.u32.u64 %0, t; }"
        : "=r"(s) : "l"(smem_dst));
    asm volatile("cp.async.ca.shared.global [%0], [%1], 16;"
                 :: "r"(s), "l"(gmem_src) : "memory");
}
__device__ __forceinline__ void cp_async_commit() {
    asm volatile("cp.async.commit_group;" ::: "memory");
}
template <int N>
__device__ __forceinline__ void cp_async_wait() {
    asm volatile("cp.async.wait_group %0;" :: "n"(N) : "memory");
}

// ---- shared acquire/release counters ----
__device__ __forceinline__ uint32_t smem_u32(const void* p) {
    uint32_t s;
    asm("{ .reg .u64 t; cvta.to.shared.u64 t, %1; cvt.u32.u64 %0, t; }"
        : "=r"(s) : "l"(p));
    return s;
}
__device__ __forceinline__ unsigned ld_acq(uint32_t a) {
    unsigned v;
    asm volatile("ld.acquire.cta.shared.u32 %0, [%1];" : "=r"(v) : "r"(a) : "memory");
    return v;
}
__device__ __forceinline__ void st_rel(uint32_t a, unsigned v) {
    asm volatile("st.release.cta.shared.u32 [%0], %1;" :: "r"(a), "r"(v) : "memory");
}

__global__ void __launch_bounds__(64, 1)
rnn_relu_kernel(const float* __restrict__ x,      // [SEQ, BATCH, 4]
                const float* __restrict__ h0,     // [1, BATCH, 3]
                const float* __restrict__ W_ih,   // [3, 4]
                const float* __restrict__ W_hh,   // [3, 3]
                const float* __restrict__ b_ih,   // [3]
                const float* __restrict__ b_hh,   // [3]
                float* __restrict__ out)
{
    extern __shared__ char smem_raw[];
    float4*   xs = (float4*)smem_raw;                   // [XS][UNR][32]
    float*    hr = (float*)(smem_raw + XS_BYTES);       // [RD][UNR][96]
    unsigned* pc = (unsigned*)(smem_raw + CTR_OFF);     // pc[0]=prod, pc[1]=cons

    const int lane = threadIdx.x & 31;
    const int warp = threadIdx.x >> 5;
    const int b0 = blockIdx.x * 32;
    const int b  = b0 + lane;

    if (threadIdx.x == 0) { pc[0] = 0; pc[1] = 0; }
    __syncthreads();   // once, before any STS traffic

    const uint32_t prod_a = smem_u32(&pc[0]);
    const uint32_t cons_a = smem_u32(&pc[1]);

    const float4* __restrict__ xv = (const float4*)x;   // [SEQ][BATCH]
    float* __restrict__ outs  = out;
    float* __restrict__ hlast = out + (size_t)SEQ * BATCH * HID;

    if (warp == 0) {
        // ================= compute warp (identical R6 math) =================
        u64 wih01[IN], whh01[HID];
        float wih2[IN], whh2[HID];
#pragma unroll
        for (int i = 0; i < IN; i++) {
            wih01[i] = pack2(W_ih[0 * IN + i], W_ih[1 * IN + i]);
            wih2[i]  = W_ih[2 * IN + i];
        }
#pragma unroll
        for (int i = 0; i < HID; i++) {
            whh01[i] = pack2(W_hh[0 * HID + i], W_hh[1 * HID + i]);
            whh2[i]  = W_hh[2 * HID + i];
        }
        const u64   bias01 = pack2(b_ih[0] + b_hh[0], b_ih[1] + b_hh[1]);
        const float bias2  = b_ih[2] + b_hh[2];

        float ha = h0[b * HID + 0];
        float hb = h0[b * HID + 1];
        float hc = h0[b * HID + 2];

        // Prime x pipeline: 3 stages = 48 timesteps lookahead.
#pragma unroll
        for (int s = 0; s < XS - 1; s++) {
#pragma unroll
            for (int k = 0; k < UNR; k++)
                cp_async16(&xs[(s * UNR + k) * 32 + lane],
                           &xv[(size_t)(s * UNR + k) * BATCH + b]);
            cp_async_commit();
        }

        for (int g = 0; g < NGRP; g++) {
            // Backpressure (never taken in steady state: store warp is faster).
            if (g >= RD) {
                while ((int)(g - ld_acq(cons_a)) >= RD) __nanosleep(64);
            }
            cp_async_wait<XS - 2>();   // this group's x complete (self-written)

            const int stage = g & (XS - 1);
            float* hrow = hr + (g & (RD - 1)) * UNR * 96;

#pragma unroll
            for (int k = 0; k < UNR; k++) {
                const float4 xt = xs[(stage * UNR + k) * 32 + lane];

                u64 p01 = fma2(wih01[0], bcast2(xt.x), bias01);
                p01 = fma2(wih01[1], bcast2(xt.y), p01);
                p01 = fma2(wih01[2], bcast2(xt.z), p01);
                p01 = fma2(wih01[3], bcast2(xt.w), p01);
                float p2 = fmaf(wih2[0], xt.x, bias2);
                p2 = fmaf(wih2[1], xt.y, p2);
                p2 = fmaf(wih2[2], xt.z, p2);
                p2 = fmaf(wih2[3], xt.w, p2);

                u64 a01 = fma2(whh01[0], bcast2(ha), p01);
                a01 = fma2(whh01[1], bcast2(hb), a01);
                a01 = fma2(whh01[2], bcast2(hc), a01);
                float a2 = fmaf(whh2[0], ha, p2);
                a2 = fmaf(whh2[1], hb, a2);
                a2 = fmaf(whh2[2], hc, a2);

                const float2 a = unpack2(a01);
                ha = fmaxf(a.x, 0.0f);
                hb = fmaxf(a.y, 0.0f);
                hc = fmaxf(a2, 0.0f);

                // Conflict-free STS (lane*3 mod 32 distinct).
                float* d = hrow + k * 96 + lane * 3;
                d[0] = ha; d[1] = hb; d[2] = hc;
            }

            // Refill stage for group g+XS-1 (group n lives in stage n&(XS-1)).
            const int gnext = g + XS - 1;
            if (gnext < NGRP) {
                const int ns = gnext & (XS - 1);
#pragma unroll
                for (int k = 0; k < UNR; k++)
                    cp_async16(&xs[(ns * UNR + k) * 32 + lane],
                               &xv[(size_t)(gnext * UNR + k) * BATCH + b]);
            }
            cp_async_commit();

            __syncwarp();                           // all lanes' STS done
            if (lane == 0) st_rel(prod_a, g + 1);   // publish group g
        }

        hlast[b * HID + 0] = ha;
        hlast[b * HID + 1] = hb;
        hlast[b * HID + 2] = hc;

    } else {
        // ================= store warp: drain h ring to gmem =================
        for (int g = 0; g < NGRP; g++) {
            while ((int)ld_acq(prod_a) <= g) __nanosleep(128);

            const float* src = hr + (g & (RD - 1)) * UNR * 96;
            if (lane < 24) {
#pragma unroll
                for (int k = 0; k < UNR; k++) {
                    const float4 v = *(const float4*)(src + k * 96 + lane * 4);
                    __stcs((float4*)(outs + ((size_t)(g * UNR + k) * BATCH + b0) * HID)
                               + lane, v);
                }
            }
            __syncwarp();                           // all reads of this slot done
            if (lane == 0) st_rel(cons_a, g + 1);   // slot reusable
        }
    }
}

extern "C" void kernel_launch(void* const* d_in, const int* in_sizes, int n_in,
                              void* d_out, int out_size)
{
    const float* x    = (const float*)d_in[0];
    const float* h0   = (const float*)d_in[1];
    const float* W_ih = (const float*)d_in[2];
    const float* W_hh = (const float*)d_in[3];
    const float* b_ih = (const float*)d_in[4];
    const float* b_hh = (const float*)d_in[5];
    float* out = (float*)d_out;

    static bool attr_set = false;
    // Idempotent attribute set (host-side, not a stream op; capture-safe).
    cudaFuncSetAttribute(rnn_relu_kernel,
                         cudaFuncAttributeMaxDynamicSharedMemorySize, SMEM_TOTAL);
    (void)attr_set;

    rnn_relu_kernel<<<BATCH / 32, 64, SMEM_TOTAL>>>(x, h0, W_ih, W_hh, b_ih, b_hh, out);
}

// round 12
// speedup vs baseline: 1.3990x; 1.3990x over previous
#include <cuda_runtime.h>
#include <cstdint>

#define SEQ    2048
#define BATCH  4096
#define IN     4
#define HID    3
#define UNR    16                 // timesteps per pipeline stage
#define STAGES 4                  // smem pipeline depth (32 KB)
#define NGRP   (SEQ / UNR)        // 128 groups

typedef unsigned long long u64;

// ---- packed f32x2 helpers (Blackwell) ----
__device__ __forceinline__ u64 pack2(float lo, float hi) {
    u64 r; asm("mov.b64 %0, {%1, %2};" : "=l"(r) : "f"(lo), "f"(hi)); return r;
}
__device__ __forceinline__ u64 bcast2(float v) {
    u64 r; asm("mov.b64 %0, {%1, %1};" : "=l"(r) : "f"(v)); return r;
}
__device__ __forceinline__ u64 fma2(u64 a, u64 b, u64 c) {
    u64 d; asm("fma.rn.f32x2 %0, %1, %2, %3;" : "=l"(d) : "l"(a), "l"(b), "l"(c)); return d;
}
__device__ __forceinline__ float2 unpack2(u64 v) {
    float2 r; asm("mov.b64 {%0, %1}, %2;" : "=f"(r.x), "=f"(r.y) : "l"(v)); return r;
}

// ---- cp.async ----
__device__ __forceinline__ void cp_async16(void* smem_dst, const void* gmem_src) {
    uint32_t s;
    asm("{ .reg .u64 t; cvta.to.shared.u64 t, %1; cvt.u32.u64 %0, t; }"
        : "=r"(s) : "l"(smem_dst));
    asm volatile("cp.async.ca.shared.global [%0], [%1], 16;"
                 :: "r"(s), "l"(gmem_src) : "memory");
}
__device__ __forceinline__ void cp_async_commit() {
    asm volatile("cp.async.commit_group;" ::: "memory");
}
template <int N>
__device__ __forceinline__ void cp_async_wait() {
    asm volatile("cp.async.wait_group %0;" :: "n"(N) : "memory");
}

__global__ void __launch_bounds__(32, 1)
rnn_relu_kernel(const float* __restrict__ x,      // [SEQ, BATCH, 4]
                const float* __restrict__ h0,     // [1, BATCH, 3]
                const float* __restrict__ W_ih,   // [3, 4]
                const float* __restrict__ W_hh,   // [3, 3]
                const float* __restrict__ b_ih,   // [3]
                const float* __restrict__ b_hh,   // [3]
                float* __restrict__ out)
{
    // One warp per block; each thread owns one batch chain. Sync-free.
    __shared__ float4 xs[STAGES][UNR][32];   // 32 KB input pipeline

    const int lane = threadIdx.x;
    const int b = blockIdx.x * 32 + lane;

    // Projection weights pre-broadcast for time-packed fma2:
    // wP[j][i] = (W_ih[j][i], W_ih[j][i]); biasP[j] likewise.
    u64 wP[HID][IN];
    u64 biasP[HID];
#pragma unroll
    for (int j = 0; j < HID; j++) {
#pragma unroll
        for (int i = 0; i < IN; i++) wP[j][i] = bcast2(W_ih[j * IN + i]);
        biasP[j] = bcast2(b_ih[j] + b_hh[j]);
    }
    // Recurrence weights packed over hidden units (0,1), unit 2 scalar (as R6).
    u64 whh01[HID];
    float whh2[HID];
#pragma unroll
    for (int i = 0; i < HID; i++) {
        whh01[i] = pack2(W_hh[0 * HID + i], W_hh[1 * HID + i]);
        whh2[i]  = W_hh[2 * HID + i];
    }

    float ha = h0[b * HID + 0];
    float hb = h0[b * HID + 1];
    float hc = h0[b * HID + 2];

    const float4* __restrict__ xv = (const float4*)x;  // [SEQ][BATCH]
    float* __restrict__ outs  = out;
    float* __restrict__ hlast = out + (size_t)SEQ * BATCH * HID;

    // Prime STAGES-1 = 3 stages (48 timesteps of lookahead).
#pragma unroll
    for (int s = 0; s < STAGES - 1; s++) {
#pragma unroll
        for (int k = 0; k < UNR; k++)
            cp_async16(&xs[s][k][lane], &xv[(size_t)(s * UNR + k) * BATCH + b]);
        cp_async_commit();
    }

    for (int g = 0; g < NGRP; g++) {
        const int stage = g & (STAGES - 1);
        cp_async_wait<STAGES - 2>();   // this stage complete (self-written smem)

        const int t0 = g * UNR;
#pragma unroll
        for (int k = 0; k < UNR; k += 2) {
            const float4 x0 = xs[stage][k + 0][lane];
            const float4 x1 = xs[stage][k + 1][lane];

            // Time-packed projection: P[j] = (p[t][j], p[t+1][j]).
            const u64 xpx = pack2(x0.x, x1.x);
            const u64 xpy = pack2(x0.y, x1.y);
            const u64 xpz = pack2(x0.z, x1.z);
            const u64 xpw = pack2(x0.w, x1.w);

            u64 P0 = fma2(wP[0][0], xpx, biasP[0]);
            u64 P1 = fma2(wP[1][0], xpx, biasP[1]);
            u64 P2 = fma2(wP[2][0], xpx, biasP[2]);
            P0 = fma2(wP[0][1], xpy, P0);
            P1 = fma2(wP[1][1], xpy, P1);
            P2 = fma2(wP[2][1], xpy, P2);
            P0 = fma2(wP[0][2], xpz, P0);
            P1 = fma2(wP[1][2], xpz, P1);
            P2 = fma2(wP[2][2], xpz, P2);
            P0 = fma2(wP[0][3], xpw, P0);
            P1 = fma2(wP[1][3], xpw, P1);
            P2 = fma2(wP[2][3], xpw, P2);

            const float2 q0 = unpack2(P0);   // (p0_t, p0_t1)
            const float2 q1 = unpack2(P1);   // (p1_t, p1_t1)
            const float2 q2 = unpack2(P2);   // (p2_t, p2_t1)
            const u64 p01_t  = pack2(q0.x, q1.x);
            const u64 p01_t1 = pack2(q0.y, q1.y);

            // ---- recurrence, timestep t (identical math/order to R6) ----
            {
                u64 a01 = fma2(whh01[0], bcast2(ha), p01_t);
                a01 = fma2(whh01[1], bcast2(hb), a01);
                a01 = fma2(whh01[2], bcast2(hc), a01);
                float a2 = fmaf(whh2[0], ha, q2.x);
                a2 = fmaf(whh2[1], hb, a2);
                a2 = fmaf(whh2[2], hc, a2);

                const float2 a = unpack2(a01);
                ha = fmaxf(a.x, 0.0f);
                hb = fmaxf(a.y, 0.0f);
                hc = fmaxf(a2, 0.0f);

                const size_t o = ((size_t)(t0 + k) * BATCH + b) * HID;
                __stcs(outs + o + 0, ha);
                __stcs(outs + o + 1, hb);
                __stcs(outs + o + 2, hc);
            }

            // ---- recurrence, timestep t+1 ----
            {
                u64 a01 = fma2(whh01[0], bcast2(ha), p01_t1);
                a01 = fma2(whh01[1], bcast2(hb), a01);
                a01 = fma2(whh01[2], bcast2(hc), a01);
                float a2 = fmaf(whh2[0], ha, q2.y);
                a2 = fmaf(whh2[1], hb, a2);
                a2 = fmaf(whh2[2], hc, a2);

                const float2 a = unpack2(a01);
                ha = fmaxf(a.x, 0.0f);
                hb = fmaxf(a.y, 0.0f);
                hc = fmaxf(a2, 0.0f);

                const size_t o = ((size_t)(t0 + k + 1) * BATCH + b) * HID;
                __stcs(outs + o + 0, ha);
                __stcs(outs + o + 1, hb);
                __stcs(outs + o + 2, hc);
            }
        }

        // Refill this stage for group g + STAGES - 1.
        const int gnext = g + STAGES - 1;
        if (gnext < NGRP) {
            const int ns = gnext & (STAGES - 1);
#pragma unroll
            for (int k = 0; k < UNR; k++)
                cp_async16(&xs[ns][k][lane],
                           &xv[(size_t)(gnext * UNR + k) * BATCH + b]);
        }
        cp_async_commit();  // uniform group accounting on the tail
    }

    hlast[b * HID + 0] = ha;
    hlast[b * HID + 1] = hb;
    hlast[b * HID + 2] = hc;
}

extern "C" void kernel_launch(void* const* d_in, const int* in_sizes, int n_in,
                              void* d_out, int out_size)
{
    const float* x    = (const float*)d_in[0];
    const float* h0   = (const float*)d_in[1];
    const float* W_ih = (const float*)d_in[2];
    const float* W_hh = (const float*)d_in[3];
    const float* b_ih = (const float*)d_in[4];
    const float* b_hh = (const float*)d_in[5];
    float* out = (float*)d_out;

    rnn_relu_kernel<<<BATCH / 32, 32>>>(x, h0, W_ih, W_hh, b_ih, b_hh, out);
}

// round 13
// speedup vs baseline: 1.4690x; 1.0500x over previous
#include <cuda_runtime.h>
#include <cstdint>

#define SEQ    2048
#define BATCH  4096
#define IN     4
#define HID    3
#define UNR    16                 // timesteps per pipeline stage
#define STAGES 4                  // smem pipeline depth (32 KB)
#define NGRP   (SEQ / UNR)        // 128 groups

typedef unsigned long long u64;

// ---- packed f32x2 helpers (Blackwell) ----
__device__ __forceinline__ u64 pack2(float lo, float hi) {
    u64 r; asm("mov.b64 %0, {%1, %2};" : "=l"(r) : "f"(lo), "f"(hi)); return r;
}
__device__ __forceinline__ u64 bcast2(float v) {
    u64 r; asm("mov.b64 %0, {%1, %1};" : "=l"(r) : "f"(v)); return r;
}
__device__ __forceinline__ u64 fma2(u64 a, u64 b, u64 c) {
    u64 d; asm("fma.rn.f32x2 %0, %1, %2, %3;" : "=l"(d) : "l"(a), "l"(b), "l"(c)); return d;
}
__device__ __forceinline__ float2 unpack2(u64 v) {
    float2 r; asm("mov.b64 {%0, %1}, %2;" : "=f"(r.x), "=f"(r.y) : "l"(v)); return r;
}

// ---- cp.async ----
__device__ __forceinline__ void cp_async16(void* smem_dst, const void* gmem_src) {
    uint32_t s;
    asm("{ .reg .u64 t; cvta.to.shared.u64 t, %1; cvt.u32.u64 %0, t; }"
        : "=r"(s) : "l"(smem_dst));
    asm volatile("cp.async.ca.shared.global [%0], [%1], 16;"
                 :: "r"(s), "l"(gmem_src) : "memory");
}
__device__ __forceinline__ void cp_async_commit() {
    asm volatile("cp.async.commit_group;" ::: "memory");
}
template <int N>
__device__ __forceinline__ void cp_async_wait() {
    asm volatile("cp.async.wait_group %0;" :: "n"(N) : "memory");
}

__global__ void __launch_bounds__(32, 1)
rnn_relu_kernel(const float* __restrict__ x,      // [SEQ, BATCH, 4]
                const float* __restrict__ h0,     // [1, BATCH, 3]
                const float* __restrict__ W_ih,   // [3, 4]
                const float* __restrict__ W_hh,   // [3, 3]
                const float* __restrict__ b_ih,   // [3]
                const float* __restrict__ b_hh,   // [3]
                float* __restrict__ out)
{
    // One warp per block; each thread owns one batch chain. Sync-free.
    __shared__ float4 xs[STAGES][UNR][32];   // 32 KB input pipeline

    const int lane = threadIdx.x;
    const int b = blockIdx.x * 32 + lane;

    // Projection weights pre-broadcast (hoisted once): wP[j][i] = (w, w).
    u64 wP[HID][IN];
    u64 biasP[HID];
#pragma unroll
    for (int j = 0; j < HID; j++) {
#pragma unroll
        for (int i = 0; i < IN; i++) wP[j][i] = bcast2(W_ih[j * IN + i]);
        biasP[j] = bcast2(b_ih[j] + b_hh[j]);
    }
    // Recurrence weights scalar (short 16-cyc chain, no packing movs).
    float whh[HID][HID];
#pragma unroll
    for (int j = 0; j < HID; j++)
#pragma unroll
        for (int i = 0; i < HID; i++) whh[j][i] = W_hh[j * HID + i];

    float ha = h0[b * HID + 0];
    float hb = h0[b * HID + 1];
    float hc = h0[b * HID + 2];

    const float4* __restrict__ xv = (const float4*)x;  // [SEQ][BATCH]
    float* __restrict__ outs  = out;
    float* __restrict__ hlast = out + (size_t)SEQ * BATCH * HID;

    // Prime STAGES-1 = 3 stages (48 timesteps of lookahead).
#pragma unroll
    for (int s = 0; s < STAGES - 1; s++) {
#pragma unroll
        for (int k = 0; k < UNR; k++)
            cp_async16(&xs[s][k][lane], &xv[(size_t)(s * UNR + k) * BATCH + b]);
        cp_async_commit();
    }

    for (int g = 0; g < NGRP; g++) {
        const int stage = g & (STAGES - 1);
        cp_async_wait<STAGES - 2>();   // this stage complete (self-written smem)

        const int t0 = g * UNR;
#pragma unroll
        for (int k = 0; k < UNR; k += 2) {
            const float4 x0 = xs[stage][k + 0][lane];
            const float4 x1 = xs[stage][k + 1][lane];

            // Time-packed projection: P[j] = (p[t][j], p[t+1][j]). Off-chain.
            const u64 xpx = pack2(x0.x, x1.x);
            const u64 xpy = pack2(x0.y, x1.y);
            const u64 xpz = pack2(x0.z, x1.z);
            const u64 xpw = pack2(x0.w, x1.w);

            u64 P0 = fma2(wP[0][0], xpx, biasP[0]);
            u64 P1 = fma2(wP[1][0], xpx, biasP[1]);
            u64 P2 = fma2(wP[2][0], xpx, biasP[2]);
            P0 = fma2(wP[0][1], xpy, P0);
            P1 = fma2(wP[1][1], xpy, P1);
            P2 = fma2(wP[2][1], xpy, P2);
            P0 = fma2(wP[0][2], xpz, P0);
            P1 = fma2(wP[1][2], xpz, P1);
            P2 = fma2(wP[2][2], xpz, P2);
            P0 = fma2(wP[0][3], xpw, P0);
            P1 = fma2(wP[1][3], xpw, P1);
            P2 = fma2(wP[2][3], xpw, P2);

            // Unpack once; scalar recurrence consumes halves directly (no repack).
            const float2 q0 = unpack2(P0);   // (p0_t, p0_t1)
            const float2 q1 = unpack2(P1);   // (p1_t, p1_t1)
            const float2 q2 = unpack2(P2);   // (p2_t, p2_t1)

            // ---- recurrence, timestep t (scalar; chain = 3 FFMA + max) ----
            {
                float a0 = fmaf(whh[0][0], ha, q0.x);
                float a1 = fmaf(whh[1][0], ha, q1.x);
                float a2 = fmaf(whh[2][0], ha, q2.x);
                a0 = fmaf(whh[0][1], hb, a0);
                a1 = fmaf(whh[1][1], hb, a1);
                a2 = fmaf(whh[2][1], hb, a2);
                a0 = fmaf(whh[0][2], hc, a0);
                a1 = fmaf(whh[1][2], hc, a1);
                a2 = fmaf(whh[2][2], hc, a2);

                ha = fmaxf(a0, 0.0f);
                hb = fmaxf(a1, 0.0f);
                hc = fmaxf(a2, 0.0f);

                const size_t o = ((size_t)(t0 + k) * BATCH + b) * HID;
                __stcs(outs + o + 0, ha);
                __stcs(outs + o + 1, hb);
                __stcs(outs + o + 2, hc);
            }

            // ---- recurrence, timestep t+1 ----
            {
                float a0 = fmaf(whh[0][0], ha, q0.y);
                float a1 = fmaf(whh[1][0], ha, q1.y);
                float a2 = fmaf(whh[2][0], ha, q2.y);
                a0 = fmaf(whh[0][1], hb, a0);
                a1 = fmaf(whh[1][1], hb, a1);
                a2 = fmaf(whh[2][1], hb, a2);
                a0 = fmaf(whh[0][2], hc, a0);
                a1 = fmaf(whh[1][2], hc, a1);
                a2 = fmaf(whh[2][2], hc, a2);

                ha = fmaxf(a0, 0.0f);
                hb = fmaxf(a1, 0.0f);
                hc = fmaxf(a2, 0.0f);

                const size_t o = ((size_t)(t0 + k + 1) * BATCH + b) * HID;
                __stcs(outs + o + 0, ha);
                __stcs(outs + o + 1, hb);
                __stcs(outs + o + 2, hc);
            }
        }

        // Refill this stage for group g + STAGES - 1.
        const int gnext = g + STAGES - 1;
        if (gnext < NGRP) {
            const int ns = gnext & (STAGES - 1);
#pragma unroll
            for (int k = 0; k < UNR; k++)
                cp_async16(&xs[ns][k][lane],
                           &xv[(size_t)(gnext * UNR + k) * BATCH + b]);
        }
        cp_async_commit();  // uniform group accounting on the tail
    }

    hlast[b * HID + 0] = ha;
    hlast[b * HID + 1] = hb;
    hlast[b * HID + 2] = hc;
}

extern "C" void kernel_launch(void* const* d_in, const int* in_sizes, int n_in,
                              void* d_out, int out_size)
{
    const float* x    = (const float*)d_in[0];
    const float* h0   = (const float*)d_in[1];
    const float* W_ih = (const float*)d_in[2];
    const float* W_hh = (const float*)d_in[3];
    const float* b_ih = (const float*)d_in[4];
    const float* b_hh = (const float*)d_in[5];
    float* out = (float*)d_out;

    rnn_relu_kernel<<<BATCH / 32, 32>>>(x, h0, W_ih, W_hh, b_ih, b_hh, out);
}